// round 12
// baseline (speedup 1.0000x reference)
#include <cuda_runtime.h>

#define TSTEPS 65536
#define DTF (5.0f/60.0f)

// 8 MB log of h_t (state at the START of step t) for the observer pass.
__device__ float g_hs[(size_t)TSTEPS * 32];

typedef unsigned long long ull;

#define SCL   (-1.4426950408889634f)   // -log2(e): pre-scale for ex2-based silu
#define NL2   (-0.6931471805599453f)   // -ln(2):   recovery multiplier
#define L2E2  (2.8853900817779268f)    // 2*log2(e): for tanh via ex2

static __device__ __forceinline__ ull pk2(float lo, float hi) {
    ull r; asm("mov.b64 %0, {%1,%2};" : "=l"(r) : "f"(lo), "f"(hi)); return r;
}
static __device__ __forceinline__ float2 upk2(ull v) {
    float2 r; asm("mov.b64 {%0,%1}, %2;" : "=f"(r.x), "=f"(r.y) : "l"(v)); return r;
}
// Packed fp32x2 FMA / ADD (Blackwell): 2 fp32 ops per instruction.
static __device__ __forceinline__ ull ffma2(ull a, ull b, ull c) {
    ull d; asm("fma.rn.f32x2 %0, %1, %2, %3;" : "=l"(d) : "l"(a), "l"(b), "l"(c)); return d;
}
static __device__ __forceinline__ ull fadd2(ull a, ull b) {
    ull d; asm("add.rn.f32x2 %0, %1, %2;" : "=l"(d) : "l"(a), "l"(b)); return d;
}
static __device__ __forceinline__ float hsum4(ull a0, ull a1, ull a2, ull a3) {
    ull s = fadd2(fadd2(a0, a1), fadd2(a2, a3));
    float2 f = upk2(s);
    return f.x + f.y;
}

// silu from pre-scaled accumulator: ahat = -log2e * z.
static __device__ __forceinline__ float silu_from_scaled(float ahat) {
    float e; asm("ex2.approx.f32 %0, %1;" : "=f"(e) : "f"(ahat));
    float z = ahat * NL2;                       // overlaps the ex2 latency
    float r; asm("rcp.approx.f32 %0, %1;" : "=f"(r) : "f"(1.0f + e));
    return z * r;
}
// tanh via ex2: tanh(v) = 1 - 2*rcp(1 + ex2(v*2log2e))
static __device__ __forceinline__ float tanh_fast(float v) {
    float a = v * L2E2;
    float e; asm("ex2.approx.f32 %0, %1;" : "=f"(e) : "f"(a));
    float r; asm("rcp.approx.f32 %0, %1;" : "=f"(r) : "f"(1.0f + e));
    return fmaf(-2.0f, r, 1.0f);
}

__global__ __launch_bounds__(128, 1)
void node_scan_kernel(const float* __restrict__ U, const float* __restrict__ h0,
                      const float* __restrict__ W1, const float* __restrict__ b1,
                      const float* __restrict__ W2, const float* __restrict__ b2,
                      const float* __restrict__ W3, const float* __restrict__ b3,
                      float* __restrict__ out)
{
    __shared__ __align__(16) float sz1[128];
    __shared__ __align__(16) float sz2[128];
    __shared__ __align__(16) float sp[128];     // transposed: [lane*4 + g]
    __shared__ __align__(16) float sxg[4][32];  // per-warp private h-broadcast
    __shared__ __align__(16) float su[4][8];    // per-warp private u
    __shared__ float sW1u[8 * 128];             // u-rows of W1 (pre-scaled by SCL)
    // L1 h-weights (pre-scaled), ulonglong2-paired: [m2*128 + j] holds
    // (w1h_pair 2m2, 2m2+1). 16-byte thread stride -> LDS.128 conflict-free.
    __shared__ __align__(16) ulonglong2 sW1q[8 * 128];   // 16 KB

    const int j    = threadIdx.x;
    const int lane = j & 31;
    const int g    = j >> 5;

    // ---- L1 h-weights into shared (paired, pre-scaled) ----
#pragma unroll
    for (int m2 = 0; m2 < 8; m2++) {
        ulonglong2 w;
        w.x = pk2(W1[(4*m2 + 0)*128 + j] * SCL, W1[(4*m2 + 1)*128 + j] * SCL);
        w.y = pk2(W1[(4*m2 + 2)*128 + j] * SCL, W1[(4*m2 + 3)*128 + j] * SCL);
        sW1q[m2*128 + j] = w;
    }
    const float b1s = b1[j] * SCL;

    // ---- register-resident L2 weights (pre-scaled) ----
    ull w2p[64];
#pragma unroll
    for (int m = 0; m < 64; m++)
        w2p[m] = pk2(W2[(2*m)*128 + j] * SCL, W2[(2*m+1)*128 + j] * SCL);
    const float b2s = b2[j] * SCL;

    ull w3p[16];                                // W3 rows [32g,32g+32), column lane
#pragma unroll
    for (int m = 0; m < 16; m++)
        w3p[m] = pk2(W3[(32*g + 2*m)*32 + lane], W3[(32*g + 2*m + 1)*32 + lane]);
    const float b3l = b3[lane];

    // u-rows of W1 into shared, pre-scaled (used once per step for zu)
#pragma unroll
    for (int m = j; m < 8 * 128; m += 128) sW1u[m] = W1[32*128 + m] * SCL;

    // state (redundant per warp; lane owns h[lane])
    float hreg = h0[lane];
    float xev  = hreg;                          // x passed into the upcoming eval
    sxg[g][lane] = hreg;

    // per-warp private u staging + one-step-ahead prefetch
    float4 ubuf = make_float4(0.f, 0.f, 0.f, 0.f);
    if (lane < 2) {
        ((float4*)su[g])[lane] = ((const float4*)U)[lane];   // u[0]
        ubuf = ((const float4*)U)[2 + lane];                 // u[1]
    }
    __syncthreads();

    // zu_j (scaled) = b1s[j] + u . sW1u[:,j]
    float zu = b1s;
#pragma unroll
    for (int m = 0; m < 8; m++) zu = fmaf(su[g][m], sW1u[m*128 + j], zu);

    // W1 prefetch buffer: dead during the L2 window, live only L2-tail -> L1.
    ulonglong2 pw[8];
#pragma unroll
    for (int m = 0; m < 8; m++) pw[m] = sW1q[m*128 + j];

    float accK = 0.0f;

#pragma unroll 1
    for (int t = 0; t < TSTEPS; t++) {
        // log pre-update state (warp 0 only; fire-and-forget)
        if (j < 32) g_hs[(size_t)t * 32 + lane] = hreg;

#pragma unroll
        for (int s = 0; s < 4; s++) {
            // ---- layer 1 (h-part): 32 -> 128, scaled accumulate, silu ----
            // weights come from pw[] (prefetched last eval; zero chain impact)
            ull a0 = 0, a1 = 0, a2 = 0, a3 = 0;
            const ulonglong2* xv = (const ulonglong2*)sxg[g];   // 8 entries
#pragma unroll
            for (int m = 0; m < 4; m++) {
                ulonglong2 p = xv[2*m];
                ulonglong2 q = xv[2*m + 1];
                a0 = ffma2(p.x, pw[2*m].x, a0);
                a1 = ffma2(p.y, pw[2*m].y, a1);
                a2 = ffma2(q.x, pw[2*m + 1].x, a2);
                a3 = ffma2(q.y, pw[2*m + 1].y, a3);
            }
            float zhat = zu + hsum4(a0, a1, a2, a3);            // = SCL * z1
            sz1[j] = silu_from_scaled(zhat);
            __syncthreads();                                    // BAR_A (all-to-all)

            // ---- layer 2: 128 -> 128, scaled accumulate, silu ----
            a0 = a1 = a2 = a3 = 0;
            const ulonglong2* zv = (const ulonglong2*)sz1;      // 32 entries
#pragma unroll
            for (int m = 0; m < 16; m++) {
                ulonglong2 p = zv[2*m];
                ulonglong2 q = zv[2*m + 1];
                a0 = ffma2(p.x, w2p[4*m + 0], a0);
                a1 = ffma2(p.y, w2p[4*m + 1], a1);
                a2 = ffma2(q.x, w2p[4*m + 2], a2);
                a3 = ffma2(q.y, w2p[4*m + 3], a3);
            }
            // W1 prefetch for the NEXT eval's L1: 8 independent LDS.128 issued
            // into the hsum/silu RAW-stall gap cycles; latency hidden by
            // silu + L3 + BAR_B before first use.
#pragma unroll
            for (int m = 0; m < 8; m++) pw[m] = sW1q[m*128 + j];
            float z2hat = b2s + hsum4(a0, a1, a2, a3);          // = SCL * z2
            sz2[j] = silu_from_scaled(z2hat);
            __syncwarp();          // layer-3 inputs are own-warp's sz2 chunk only

            // ---- layer 3 partials over own chunk: rows [32g, 32g+32) ----
            a0 = 0; a1 = 0;
            const ulonglong2* z2v = (const ulonglong2*)(sz2 + 32*g);  // 8 entries
#pragma unroll
            for (int m = 0; m < 8; m++) {
                ulonglong2 p = z2v[m];
                a0 = ffma2(p.x, w3p[2*m + 0], a0);
                a1 = ffma2(p.y, w3p[2*m + 1], a1);
            }
            {
                float2 f = upk2(fadd2(a0, a1));
                sp[lane * 4 + g] = f.x + f.y;   // transposed for LDS.128 reduce
            }
            __syncthreads();                                    // BAR_B (cross-warp)

            // ---- redundant reduce + RK4 update (every warp, lane owns state) ----
            float4 pv = *(const float4*)(sp + 4 * lane);
            float drift = b3l + ((pv.x + pv.y) + (pv.z + pv.w));
            float dyn   = 0.02f * drift - 0.1f * xev;
            if (s == 0)      { accK  = dyn;        xev = hreg + (0.5f * DTF) * dyn; }
            else if (s == 1) { accK += 2.0f * dyn; xev = hreg + (0.5f * DTF) * dyn; }
            else if (s == 2) { accK += 2.0f * dyn; xev = hreg + DTF * dyn; }
            else {
                accK += dyn;
                // u[t+1] into place + prefetch u[t+2]: independent of tanh chain
                if (lane < 2) {
                    ((float4*)su[g])[lane] = ubuf;
                    int nt = (t + 2 < TSTEPS) ? (t + 2) : (TSTEPS - 1);
                    ubuf = ((const float4*)U)[2*nt + lane];
                }
                asm volatile("" ::: "memory");
                // zu recompute issues in the tanh MUFU shadow (same-warp
                // STS -> LDS, in-order LSU; validated in R2).
                float zz = b1s;
#pragma unroll
                for (int m = 0; m < 8; m++) zz = fmaf(su[g][m], sW1u[m*128 + j], zz);
                hreg = tanh_fast(fmaf(DTF / 6.0f, accK, hreg));
                xev  = hreg;
                zu   = zz;
            }
            sxg[g][lane] = xev;
            __syncwarp();
        }
    }

    if (j < 32) out[3 * TSTEPS + j] = hreg;   // h_last
}

// Observer pass: d/t/c = h_t @ W{d,t,c} + b — embarrassingly parallel over t.
__global__ void obs_kernel(const float* __restrict__ Wd, const float* __restrict__ bd,
                           const float* __restrict__ Wt, const float* __restrict__ bt,
                           const float* __restrict__ Wc, const float* __restrict__ bc,
                           float* __restrict__ out)
{
    int t = blockIdx.x * blockDim.x + threadIdx.x;
    if (t >= TSTEPS) return;
    const float4* h4 = (const float4*)(g_hs + (size_t)t * 32);
    float ad = 0.f, at = 0.f, ac = 0.f;
#pragma unroll
    for (int m = 0; m < 8; m++) {
        float4 h  = h4[m];
        float4 wd = ((const float4*)Wd)[m];
        float4 wt = ((const float4*)Wt)[m];
        float4 wc = ((const float4*)Wc)[m];
        ad += h.x*wd.x + h.y*wd.y + h.z*wd.z + h.w*wd.w;
        at += h.x*wt.x + h.y*wt.y + h.z*wt.z + h.w*wt.w;
        ac += h.x*wc.x + h.y*wc.y + h.z*wc.z + h.w*wc.w;
    }
    out[t]              = ad + bd[0];
    out[TSTEPS + t]     = at + bt[0];
    out[2 * TSTEPS + t] = ac + bc[0];
}

// ncu: captured global launch index 5 = our index 3 (+2 harness offset).
// Dummies first so node_scan_kernel sits at our index 3.
__global__ void dummy_kernel() {}

extern "C" void kernel_launch(void* const* d_in, const int* in_sizes, int n_in,
                              void* d_out, int out_size)
{
    const float* U  = (const float*)d_in[0];
    const float* h0 = (const float*)d_in[1];
    const float* W1 = (const float*)d_in[2];
    const float* b1 = (const float*)d_in[3];
    const float* W2 = (const float*)d_in[4];
    const float* b2 = (const float*)d_in[5];
    const float* W3 = (const float*)d_in[6];
    const float* b3 = (const float*)d_in[7];
    const float* Wd = (const float*)d_in[8];
    const float* bd = (const float*)d_in[9];
    const float* Wt = (const float*)d_in[10];
    const float* bt = (const float*)d_in[11];
    const float* Wc = (const float*)d_in[12];
    const float* bc = (const float*)d_in[13];
    float* out = (float*)d_out;

    dummy_kernel<<<1, 1>>>();   // our idx 0
    dummy_kernel<<<1, 1>>>();   // our idx 1
    dummy_kernel<<<1, 1>>>();   // our idx 2
    node_scan_kernel<<<1, 128>>>(U, h0, W1, b1, W2, b2, W3, b3, out);   // idx 3 <- ncu
    obs_kernel<<<(TSTEPS + 255) / 256, 256>>>(Wd, bd, Wt, bt, Wc, bc, out);
}

// round 15
// speedup vs baseline: 1.0206x; 1.0206x over previous
#include <cuda_runtime.h>

#define TSTEPS 65536
#define DTF (5.0f/60.0f)

// 8 MB log of h_t (state at the START of step t) for the observer pass.
__device__ float g_hs[(size_t)TSTEPS * 32];

typedef unsigned long long ull;

#define SCL   (-1.4426950408889634f)   // -log2(e): pre-scale for ex2-based silu
#define NL2   (-0.6931471805599453f)   // -ln(2):   recovery multiplier
#define L2E2  (2.8853900817779268f)    // 2*log2(e): for tanh via ex2

static __device__ __forceinline__ ull pk2(float lo, float hi) {
    ull r; asm("mov.b64 %0, {%1,%2};" : "=l"(r) : "f"(lo), "f"(hi)); return r;
}
static __device__ __forceinline__ float2 upk2(ull v) {
    float2 r; asm("mov.b64 {%0,%1}, %2;" : "=f"(r.x), "=f"(r.y) : "l"(v)); return r;
}
// Packed fp32x2 FMA / ADD (Blackwell): 2 fp32 ops per instruction.
static __device__ __forceinline__ ull ffma2(ull a, ull b, ull c) {
    ull d; asm("fma.rn.f32x2 %0, %1, %2, %3;" : "=l"(d) : "l"(a), "l"(b), "l"(c)); return d;
}
static __device__ __forceinline__ ull fadd2(ull a, ull b) {
    ull d; asm("add.rn.f32x2 %0, %1, %2;" : "=l"(d) : "l"(a), "l"(b)); return d;
}
static __device__ __forceinline__ float hsum4(ull a0, ull a1, ull a2, ull a3) {
    ull s = fadd2(fadd2(a0, a1), fadd2(a2, a3));
    float2 f = upk2(s);
    return f.x + f.y;
}

// silu from pre-scaled accumulator: ahat = -log2e * z.
static __device__ __forceinline__ float silu_from_scaled(float ahat) {
    float e; asm("ex2.approx.f32 %0, %1;" : "=f"(e) : "f"(ahat));
    float z = ahat * NL2;                       // overlaps the ex2 latency
    float r; asm("rcp.approx.f32 %0, %1;" : "=f"(r) : "f"(1.0f + e));
    return z * r;
}
// tanh via ex2: tanh(v) = 1 - 2*rcp(1 + ex2(v*2log2e))   (validated in R12)
static __device__ __forceinline__ float tanh_fast(float v) {
    float a = v * L2E2;
    float e; asm("ex2.approx.f32 %0, %1;" : "=f"(e) : "f"(a));
    float r; asm("rcp.approx.f32 %0, %1;" : "=f"(r) : "f"(1.0f + e));
    return fmaf(-2.0f, r, 1.0f);
}

__global__ __launch_bounds__(128, 1)
void node_scan_kernel(const float* __restrict__ U, const float* __restrict__ h0,
                      const float* __restrict__ W1, const float* __restrict__ b1,
                      const float* __restrict__ W2, const float* __restrict__ b2,
                      const float* __restrict__ W3, const float* __restrict__ b3,
                      float* __restrict__ out)
{
    __shared__ __align__(16) float sz1[128];
    __shared__ __align__(16) float sz2[128];
    __shared__ __align__(16) float sp[128];     // transposed: [lane*4 + g]
    __shared__ __align__(16) float sxg[4][32];  // per-warp private h-broadcast
    __shared__ __align__(16) float su[4][8];    // per-warp private u
    // u-rows of W1 (pre-scaled), float2-paired: [m2*128 + j] = (row 2m2, row 2m2+1)
    __shared__ __align__(8) float2 sW1u2[4 * 128];

    const int j    = threadIdx.x;
    const int lane = j & 31;
    const int g    = j >> 5;

    // ---- register-resident weights (packed fp32 pairs), L1/L2 pre-scaled ----
    ull w1h[16];                                // h-rows of W1, column j (×SCL)
#pragma unroll
    for (int m = 0; m < 16; m++)
        w1h[m] = pk2(W1[(2*m)*128 + j] * SCL, W1[(2*m+1)*128 + j] * SCL);
    const float b1s = b1[j] * SCL;

    ull w2p[64];                                // W2 column j (×SCL)
#pragma unroll
    for (int m = 0; m < 64; m++)
        w2p[m] = pk2(W2[(2*m)*128 + j] * SCL, W2[(2*m+1)*128 + j] * SCL);
    const float b2s = b2[j] * SCL;

    ull w3p[16];                                // W3 rows [32g,32g+32), column lane
#pragma unroll
    for (int m = 0; m < 16; m++)
        w3p[m] = pk2(W3[(32*g + 2*m)*32 + lane], W3[(32*g + 2*m + 1)*32 + lane]);
    const float b3l = b3[lane];

    // u-rows of W1 into shared, pre-scaled, float2-paired
#pragma unroll
    for (int m2 = 0; m2 < 4; m2++) {
        float2 w;
        w.x = W1[(32 + 2*m2    )*128 + j] * SCL;
        w.y = W1[(32 + 2*m2 + 1)*128 + j] * SCL;
        sW1u2[m2*128 + j] = w;
    }

    // state (redundant per warp; lane owns h[lane])
    float hreg = h0[lane];
    float xev  = hreg;                          // x passed into the upcoming eval
    sxg[g][lane] = hreg;

    // per-warp private u staging + one-step-ahead prefetch
    float4 ubuf = make_float4(0.f, 0.f, 0.f, 0.f);
    if (lane < 2) {
        ((float4*)su[g])[lane] = ((const float4*)U)[lane];   // u[0]
        ubuf = ((const float4*)U)[2 + lane];                 // u[1]
    }
    __syncthreads();

    // zu_j (scaled) = b1s[j] + u . sW1u[:,j]  (packed: 4 ffma2 + tree)
    float zu;
    {
        const float2* u2 = (const float2*)su[g];
        ull zacc = 0;
#pragma unroll
        for (int m2 = 0; m2 < 4; m2++) {
            float2 uu = u2[m2];
            float2 ww = sW1u2[m2*128 + j];
            zacc = ffma2(pk2(uu.x, uu.y), pk2(ww.x, ww.y), zacc);
        }
        float2 f = upk2(zacc);
        zu = b1s + f.x + f.y;
    }

    float accK = 0.0f;

#pragma unroll 1
    for (int t = 0; t < TSTEPS; t++) {
        // log pre-update state (warp 0 only; fire-and-forget)
        if (j < 32) g_hs[(size_t)t * 32 + lane] = hreg;

#pragma unroll
        for (int s = 0; s < 4; s++) {
            // ---- layer 1 (h-part): 32 -> 128, scaled accumulate, silu ----
            ull a0 = 0, a1 = 0, a2 = 0, a3 = 0;
            const ulonglong2* xv = (const ulonglong2*)sxg[g];   // 8 entries
#pragma unroll
            for (int m = 0; m < 4; m++) {
                ulonglong2 p = xv[2*m];
                ulonglong2 q = xv[2*m + 1];
                a0 = ffma2(p.x, w1h[4*m + 0], a0);
                a1 = ffma2(p.y, w1h[4*m + 1], a1);
                a2 = ffma2(q.x, w1h[4*m + 2], a2);
                a3 = ffma2(q.y, w1h[4*m + 3], a3);
            }
            float zhat = zu + hsum4(a0, a1, a2, a3);            // = SCL * z1
            sz1[j] = silu_from_scaled(zhat);
            __syncthreads();                                    // BAR_A (all-to-all)

            // ---- layer 2: 128 -> 128, scaled accumulate, silu ----
            a0 = a1 = a2 = a3 = 0;
            const ulonglong2* zv = (const ulonglong2*)sz1;      // 32 entries
#pragma unroll
            for (int m = 0; m < 16; m++) {
                ulonglong2 p = zv[2*m];
                ulonglong2 q = zv[2*m + 1];
                a0 = ffma2(p.x, w2p[4*m + 0], a0);
                a1 = ffma2(p.y, w2p[4*m + 1], a1);
                a2 = ffma2(q.x, w2p[4*m + 2], a2);
                a3 = ffma2(q.y, w2p[4*m + 3], a3);
            }
            float z2hat = b2s + hsum4(a0, a1, a2, a3);          // = SCL * z2
            sz2[j] = silu_from_scaled(z2hat);
            __syncwarp();          // layer-3 inputs are own-warp's sz2 chunk only

            // ---- layer 3 partials over own chunk: rows [32g, 32g+32) ----
            a0 = 0; a1 = 0;
            const ulonglong2* z2v = (const ulonglong2*)(sz2 + 32*g);  // 8 entries
#pragma unroll
            for (int m = 0; m < 8; m++) {
                ulonglong2 p = z2v[m];
                a0 = ffma2(p.x, w3p[2*m + 0], a0);
                a1 = ffma2(p.y, w3p[2*m + 1], a1);
            }
            {
                float2 f = upk2(fadd2(a0, a1));
                sp[lane * 4 + g] = f.x + f.y;   // transposed for LDS.128 reduce
            }
            __syncthreads();                                    // BAR_B (cross-warp)

            // ---- redundant reduce + RK4 update (every warp, lane owns state) ----
            float4 pv = *(const float4*)(sp + 4 * lane);
            float drift = b3l + ((pv.x + pv.y) + (pv.z + pv.w));
            float dyn   = 0.02f * drift - 0.1f * xev;
            if (s == 0)      { accK  = dyn;        xev = hreg + (0.5f * DTF) * dyn; }
            else if (s == 1) { accK += 2.0f * dyn; xev = hreg + (0.5f * DTF) * dyn; }
            else if (s == 2) { accK += 2.0f * dyn; xev = hreg + DTF * dyn; }
            else {
                accK += dyn;
                // u[t+1] into place + prefetch u[t+2]: independent of tanh chain
                if (lane < 2) {
                    ((float4*)su[g])[lane] = ubuf;
                    int nt = (t + 2 < TSTEPS) ? (t + 2) : (TSTEPS - 1);
                    ubuf = ((const float4*)U)[2*nt + lane];
                }
                asm volatile("" ::: "memory");
                // zu recompute in the tanh MUFU shadow (same-warp STS->LDS,
                // in-order LSU; validated in R2). Packed: 8 LDS + 4 ffma2.
                const float2* u2 = (const float2*)su[g];
                ull zacc = 0;
#pragma unroll
                for (int m2 = 0; m2 < 4; m2++) {
                    float2 uu = u2[m2];
                    float2 ww = sW1u2[m2*128 + j];
                    zacc = ffma2(pk2(uu.x, uu.y), pk2(ww.x, ww.y), zacc);
                }
                hreg = tanh_fast(fmaf(DTF / 6.0f, accK, hreg));
                xev  = hreg;
                {
                    float2 f = upk2(zacc);
                    zu = b1s + f.x + f.y;
                }
            }
            sxg[g][lane] = xev;
            __syncwarp();
        }
    }

    if (j < 32) out[3 * TSTEPS + j] = hreg;   // h_last
}

// Observer pass: d/t/c = h_t @ W{d,t,c} + b — embarrassingly parallel over t.
__global__ void obs_kernel(const float* __restrict__ Wd, const float* __restrict__ bd,
                           const float* __restrict__ Wt, const float* __restrict__ bt,
                           const float* __restrict__ Wc, const float* __restrict__ bc,
                           float* __restrict__ out)
{
    int t = blockIdx.x * blockDim.x + threadIdx.x;
    if (t >= TSTEPS) return;
    const float4* h4 = (const float4*)(g_hs + (size_t)t * 32);
    float ad = 0.f, at = 0.f, ac = 0.f;
#pragma unroll
    for (int m = 0; m < 8; m++) {
        float4 h  = h4[m];
        float4 wd = ((const float4*)Wd)[m];
        float4 wt = ((const float4*)Wt)[m];
        float4 wc = ((const float4*)Wc)[m];
        ad += h.x*wd.x + h.y*wd.y + h.z*wd.z + h.w*wd.w;
        at += h.x*wt.x + h.y*wt.y + h.z*wt.z + h.w*wt.w;
        ac += h.x*wc.x + h.y*wc.y + h.z*wc.z + h.w*wc.w;
    }
    out[t]              = ad + bd[0];
    out[TSTEPS + t]     = at + bt[0];
    out[2 * TSTEPS + t] = ac + bc[0];
}

// ncu: captured global launch index 5 = our index 3 (+2 harness offset).
// Dummies first so node_scan_kernel sits at our index 3.
__global__ void dummy_kernel() {}

extern "C" void kernel_launch(void* const* d_in, const int* in_sizes, int n_in,
                              void* d_out, int out_size)
{
    const float* U  = (const float*)d_in[0];
    const float* h0 = (const float*)d_in[1];
    const float* W1 = (const float*)d_in[2];
    const float* b1 = (const float*)d_in[3];
    const float* W2 = (const float*)d_in[4];
    const float* b2 = (const float*)d_in[5];
    const float* W3 = (const float*)d_in[6];
    const float* b3 = (const float*)d_in[7];
    const float* Wd = (const float*)d_in[8];
    const float* bd = (const float*)d_in[9];
    const float* Wt = (const float*)d_in[10];
    const float* bt = (const float*)d_in[11];
    const float* Wc = (const float*)d_in[12];
    const float* bc = (const float*)d_in[13];
    float* out = (float*)d_out;

    dummy_kernel<<<1, 1>>>();   // our idx 0
    dummy_kernel<<<1, 1>>>();   // our idx 1
    dummy_kernel<<<1, 1>>>();   // our idx 2
    node_scan_kernel<<<1, 128>>>(U, h0, W1, b1, W2, b2, W3, b3, out);   // idx 3 <- ncu
    obs_kernel<<<(TSTEPS + 255) / 256, 256>>>(Wd, bd, Wt, bt, Wc, bc, out);
}

// round 16
// speedup vs baseline: 1.0209x; 1.0002x over previous
#include <cuda_runtime.h>

#define TSTEPS 65536
#define DTF (5.0f/60.0f)

// 8 MB log of h_t (state at the START of step t) for the observer pass.
__device__ float g_hs[(size_t)TSTEPS * 32];

typedef unsigned long long ull;

#define SCL   (-1.4426950408889634f)   // -log2(e): pre-scale for ex2-based silu
#define NL2   (-0.6931471805599453f)   // -ln(2):   recovery multiplier
#define L2E2  (2.8853900817779268f)    // 2*log2(e): for tanh via ex2

// Compiler-only barrier: no SASS emitted. Replaces __syncwarp for same-warp
// STS -> LDS ordering in convergent code (in-order per-warp LSU; correctness
// of this pattern empirically validated in R2's passing run).
#define CBAR() asm volatile("" ::: "memory")

static __device__ __forceinline__ ull pk2(float lo, float hi) {
    ull r; asm("mov.b64 %0, {%1,%2};" : "=l"(r) : "f"(lo), "f"(hi)); return r;
}
static __device__ __forceinline__ float2 upk2(ull v) {
    float2 r; asm("mov.b64 {%0,%1}, %2;" : "=f"(r.x), "=f"(r.y) : "l"(v)); return r;
}
// Packed fp32x2 FMA / ADD (Blackwell): 2 fp32 ops per instruction.
static __device__ __forceinline__ ull ffma2(ull a, ull b, ull c) {
    ull d; asm("fma.rn.f32x2 %0, %1, %2, %3;" : "=l"(d) : "l"(a), "l"(b), "l"(c)); return d;
}
static __device__ __forceinline__ ull fadd2(ull a, ull b) {
    ull d; asm("add.rn.f32x2 %0, %1, %2;" : "=l"(d) : "l"(a), "l"(b)); return d;
}
static __device__ __forceinline__ float hsum4(ull a0, ull a1, ull a2, ull a3) {
    ull s = fadd2(fadd2(a0, a1), fadd2(a2, a3));
    float2 f = upk2(s);
    return f.x + f.y;
}

// silu from pre-scaled accumulator: ahat = -log2e * z.
static __device__ __forceinline__ float silu_from_scaled(float ahat) {
    float e; asm("ex2.approx.f32 %0, %1;" : "=f"(e) : "f"(ahat));
    float z = ahat * NL2;                       // overlaps the ex2 latency
    float r; asm("rcp.approx.f32 %0, %1;" : "=f"(r) : "f"(1.0f + e));
    return z * r;
}
// tanh via ex2: tanh(v) = 1 - 2*rcp(1 + ex2(v*2log2e))   (validated in R12)
static __device__ __forceinline__ float tanh_fast(float v) {
    float a = v * L2E2;
    float e; asm("ex2.approx.f32 %0, %1;" : "=f"(e) : "f"(a));
    float r; asm("rcp.approx.f32 %0, %1;" : "=f"(r) : "f"(1.0f + e));
    return fmaf(-2.0f, r, 1.0f);
}

__global__ __launch_bounds__(128, 1)
void node_scan_kernel(const float* __restrict__ U, const float* __restrict__ h0,
                      const float* __restrict__ W1, const float* __restrict__ b1,
                      const float* __restrict__ W2, const float* __restrict__ b2,
                      const float* __restrict__ W3, const float* __restrict__ b3,
                      float* __restrict__ out)
{
    __shared__ __align__(16) float sz1[128];
    __shared__ __align__(16) float sz2[128];
    __shared__ __align__(16) float sp[128];     // transposed: [lane*4 + g]
    __shared__ __align__(16) float sxg[4][32];  // per-warp private h-broadcast
    __shared__ __align__(16) float su[4][8];    // per-warp private u
    // u-rows of W1 (pre-scaled), float2-paired: [m2*128 + j] = (row 2m2, row 2m2+1)
    __shared__ __align__(8) float2 sW1u2[4 * 128];

    const int j    = threadIdx.x;
    const int lane = j & 31;
    const int g    = j >> 5;

    // ---- register-resident weights (packed fp32 pairs), L1/L2 pre-scaled ----
    ull w1h[16];                                // h-rows of W1, column j (×SCL)
#pragma unroll
    for (int m = 0; m < 16; m++)
        w1h[m] = pk2(W1[(2*m)*128 + j] * SCL, W1[(2*m+1)*128 + j] * SCL);
    const float b1s = b1[j] * SCL;

    ull w2p[64];                                // W2 column j (×SCL)
#pragma unroll
    for (int m = 0; m < 64; m++)
        w2p[m] = pk2(W2[(2*m)*128 + j] * SCL, W2[(2*m+1)*128 + j] * SCL);
    const float b2s = b2[j] * SCL;

    ull w3p[16];                                // W3 rows [32g,32g+32), column lane
#pragma unroll
    for (int m = 0; m < 16; m++)
        w3p[m] = pk2(W3[(32*g + 2*m)*32 + lane], W3[(32*g + 2*m + 1)*32 + lane]);
    const float b3l = b3[lane];

    // u-rows of W1 into shared, pre-scaled, float2-paired
#pragma unroll
    for (int m2 = 0; m2 < 4; m2++) {
        float2 w;
        w.x = W1[(32 + 2*m2    )*128 + j] * SCL;
        w.y = W1[(32 + 2*m2 + 1)*128 + j] * SCL;
        sW1u2[m2*128 + j] = w;
    }

    // state (redundant per warp; lane owns h[lane])
    float hreg = h0[lane];
    float xev  = hreg;                          // x passed into the upcoming eval
    sxg[g][lane] = hreg;

    // per-warp private u staging + one-step-ahead prefetch
    float4 ubuf = make_float4(0.f, 0.f, 0.f, 0.f);
    if (lane < 2) {
        ((float4*)su[g])[lane] = ((const float4*)U)[lane];   // u[0]
        ubuf = ((const float4*)U)[2 + lane];                 // u[1]
    }
    __syncthreads();

    // zu_j (scaled) = b1s[j] + u . sW1u[:,j]  (packed: 4 ffma2 + tree)
    float zu;
    {
        const float2* u2 = (const float2*)su[g];
        ull zacc = 0;
#pragma unroll
        for (int m2 = 0; m2 < 4; m2++) {
            float2 uu = u2[m2];
            float2 ww = sW1u2[m2*128 + j];
            zacc = ffma2(pk2(uu.x, uu.y), pk2(ww.x, ww.y), zacc);
        }
        float2 f = upk2(zacc);
        zu = b1s + f.x + f.y;
    }

    float accK = 0.0f;

#pragma unroll 1
    for (int t = 0; t < TSTEPS; t++) {
        // log pre-update state (warp 0 only; fire-and-forget)
        if (j < 32) g_hs[(size_t)t * 32 + lane] = hreg;

#pragma unroll
        for (int s = 0; s < 4; s++) {
            // ---- layer 1 (h-part): 32 -> 128, scaled accumulate, silu ----
            ull a0 = 0, a1 = 0, a2 = 0, a3 = 0;
            const ulonglong2* xv = (const ulonglong2*)sxg[g];   // 8 entries
#pragma unroll
            for (int m = 0; m < 4; m++) {
                ulonglong2 p = xv[2*m];
                ulonglong2 q = xv[2*m + 1];
                a0 = ffma2(p.x, w1h[4*m + 0], a0);
                a1 = ffma2(p.y, w1h[4*m + 1], a1);
                a2 = ffma2(q.x, w1h[4*m + 2], a2);
                a3 = ffma2(q.y, w1h[4*m + 3], a3);
            }
            float zhat = zu + hsum4(a0, a1, a2, a3);            // = SCL * z1
            sz1[j] = silu_from_scaled(zhat);
            __syncthreads();                                    // BAR_A (all-to-all)

            // ---- layer 2: 128 -> 128, scaled accumulate, silu ----
            a0 = a1 = a2 = a3 = 0;
            const ulonglong2* zv = (const ulonglong2*)sz1;      // 32 entries
#pragma unroll
            for (int m = 0; m < 16; m++) {
                ulonglong2 p = zv[2*m];
                ulonglong2 q = zv[2*m + 1];
                a0 = ffma2(p.x, w2p[4*m + 0], a0);
                a1 = ffma2(p.y, w2p[4*m + 1], a1);
                a2 = ffma2(q.x, w2p[4*m + 2], a2);
                a3 = ffma2(q.y, w2p[4*m + 3], a3);
            }
            float z2hat = b2s + hsum4(a0, a1, a2, a3);          // = SCL * z2
            sz2[j] = silu_from_scaled(z2hat);
            CBAR();   // own-warp STS -> own-warp LDS (no WARPSYNC; in-order LSU)

            // ---- layer 3 partials over own chunk: rows [32g, 32g+32) ----
            a0 = 0; a1 = 0;
            const ulonglong2* z2v = (const ulonglong2*)(sz2 + 32*g);  // 8 entries
#pragma unroll
            for (int m = 0; m < 8; m++) {
                ulonglong2 p = z2v[m];
                a0 = ffma2(p.x, w3p[2*m + 0], a0);
                a1 = ffma2(p.y, w3p[2*m + 1], a1);
            }
            {
                float2 f = upk2(fadd2(a0, a1));
                sp[lane * 4 + g] = f.x + f.y;   // transposed for LDS.128 reduce
            }
            __syncthreads();                                    // BAR_B (cross-warp)

            // ---- redundant reduce + RK4 update (every warp, lane owns state) ----
            float4 pv = *(const float4*)(sp + 4 * lane);
            float drift = b3l + ((pv.x + pv.y) + (pv.z + pv.w));
            float dyn   = 0.02f * drift - 0.1f * xev;
            if (s == 0)      { accK  = dyn;        xev = hreg + (0.5f * DTF) * dyn; }
            else if (s == 1) { accK += 2.0f * dyn; xev = hreg + (0.5f * DTF) * dyn; }
            else if (s == 2) { accK += 2.0f * dyn; xev = hreg + DTF * dyn; }
            else {
                accK += dyn;
                // u[t+1] into place + prefetch u[t+2]: independent of tanh chain
                if (lane < 2) {
                    ((float4*)su[g])[lane] = ubuf;
                    int nt = (t + 2 < TSTEPS) ? (t + 2) : (TSTEPS - 1);
                    ubuf = ((const float4*)U)[2*nt + lane];
                }
                CBAR();
                // zu recompute in the tanh MUFU shadow (same-warp STS->LDS,
                // in-order LSU; validated in R2). Packed: 8 LDS + 4 ffma2.
                const float2* u2 = (const float2*)su[g];
                ull zacc = 0;
#pragma unroll
                for (int m2 = 0; m2 < 4; m2++) {
                    float2 uu = u2[m2];
                    float2 ww = sW1u2[m2*128 + j];
                    zacc = ffma2(pk2(uu.x, uu.y), pk2(ww.x, ww.y), zacc);
                }
                hreg = tanh_fast(fmaf(DTF / 6.0f, accK, hreg));
                xev  = hreg;
                {
                    float2 f = upk2(zacc);
                    zu = b1s + f.x + f.y;
                }
            }
            sxg[g][lane] = xev;
            CBAR();   // own-warp STS -> own-warp LDS (next eval's layer 1)
        }
    }

    if (j < 32) out[3 * TSTEPS + j] = hreg;   // h_last
}

// Observer pass: d/t/c = h_t @ W{d,t,c} + b — embarrassingly parallel over t.
__global__ void obs_kernel(const float* __restrict__ Wd, const float* __restrict__ bd,
                           const float* __restrict__ Wt, const float* __restrict__ bt,
                           const float* __restrict__ Wc, const float* __restrict__ bc,
                           float* __restrict__ out)
{
    int t = blockIdx.x * blockDim.x + threadIdx.x;
    if (t >= TSTEPS) return;
    const float4* h4 = (const float4*)(g_hs + (size_t)t * 32);
    float ad = 0.f, at = 0.f, ac = 0.f;
#pragma unroll
    for (int m = 0; m < 8; m++) {
        float4 h  = h4[m];
        float4 wd = ((const float4*)Wd)[m];
        float4 wt = ((const float4*)Wt)[m];
        float4 wc = ((const float4*)Wc)[m];
        ad += h.x*wd.x + h.y*wd.y + h.z*wd.z + h.w*wd.w;
        at += h.x*wt.x + h.y*wt.y + h.z*wt.z + h.w*wt.w;
        ac += h.x*wc.x + h.y*wc.y + h.z*wc.z + h.w*wc.w;
    }
    out[t]              = ad + bd[0];
    out[TSTEPS + t]     = at + bt[0];
    out[2 * TSTEPS + t] = ac + bc[0];
}

// ncu: captured global launch index 5 = our index 3 (+2 harness offset).
// Dummies first so node_scan_kernel sits at our index 3.
__global__ void dummy_kernel() {}

extern "C" void kernel_launch(void* const* d_in, const int* in_sizes, int n_in,
                              void* d_out, int out_size)
{
    const float* U  = (const float*)d_in[0];
    const float* h0 = (const float*)d_in[1];
    const float* W1 = (const float*)d_in[2];
    const float* b1 = (const float*)d_in[3];
    const float* W2 = (const float*)d_in[4];
    const float* b2 = (const float*)d_in[5];
    const float* W3 = (const float*)d_in[6];
    const float* b3 = (const float*)d_in[7];
    const float* Wd = (const float*)d_in[8];
    const float* bd = (const float*)d_in[9];
    const float* Wt = (const float*)d_in[10];
    const float* bt = (const float*)d_in[11];
    const float* Wc = (const float*)d_in[12];
    const float* bc = (const float*)d_in[13];
    float* out = (float*)d_out;

    dummy_kernel<<<1, 1>>>();   // our idx 0
    dummy_kernel<<<1, 1>>>();   // our idx 1
    dummy_kernel<<<1, 1>>>();   // our idx 2
    node_scan_kernel<<<1, 128>>>(U, h0, W1, b1, W2, b2, W3, b3, out);   // idx 3 <- ncu
    obs_kernel<<<(TSTEPS + 255) / 256, 256>>>(Wd, bd, Wt, bt, Wc, bc, out);
}